// round 12
// baseline (speedup 1.0000x reference)
#include <cuda_runtime.h>
#include <cuda_bf16.h>

// ---------------------------------------------------------------------------
// Problem constants
// ---------------------------------------------------------------------------
#define Bsz   64
#define Ssz   512
#define Dd    256
#define PEc   512
#define Mrows (Bsz * Ssz)          // 32768
#define P2    100                  // 2*P
#define F3D   768                  // 3*D

#define OFF_SUB  0
#define OFF_PO   (Bsz * 2 * Ssz)                 // 65536
#define OFF_MASK (OFF_PO + Bsz * P2 * Ssz)       // 3342336

// ---------------------------------------------------------------------------
// Scratch (static __device__ globals; no allocation allowed)
// ---------------------------------------------------------------------------
__device__ float g_embed[(size_t)Mrows * PEc];   // 64 MB
__device__ float g_xa[(size_t)Mrows * Dd];       // 32 MB
__device__ float g_xb[(size_t)Mrows * Dd];       // 32 MB
__device__ float g_maskf[Mrows];
__device__ float g_vec[Bsz * 512];
__device__ float g_sum[F3D];
__device__ float g_sumsq[F3D];
__device__ float g_scale[F3D];
__device__ float g_shift[F3D];
__device__ float g_weff[F3D * P2];
__device__ float g_beff[128];
__device__ float g_c[Bsz * 128];

__device__ __forceinline__ float sigmoidf_(float x) {
    return 1.0f / (1.0f + __expf(-x));
}

// ---------------------------------------------------------------------------
// Embedding + mask:  embed[m,:] = concat(char[inp], word[inpw]) + pos[pidx]
// ---------------------------------------------------------------------------
__global__ void embed_kernel(const int* __restrict__ inputs,
                             const int* __restrict__ words,
                             const int* __restrict__ pos,
                             const float* __restrict__ ctab,
                             const float* __restrict__ wtab,
                             const float* __restrict__ ptab,
                             float* __restrict__ out_mask) {
    int m = blockIdx.x;
    int c = threadIdx.x * 4;
    int ci = inputs[m];
    int wi = words[m];
    int pi = pos[m];
    float4 e;
    if (c < 256) {
        e = *(const float4*)(ctab + (size_t)ci * 256 + c);
    } else {
        e = *(const float4*)(wtab + (size_t)wi * 256 + (c - 256));
    }
    float4 pv = *(const float4*)(ptab + (size_t)pi * 512 + c);
    e.x += pv.x; e.y += pv.y; e.z += pv.z; e.w += pv.w;
    *(float4*)(g_embed + (size_t)m * 512 + c) = e;
    if (threadIdx.x == 0) {
        float mv = (ci != 0) ? 1.0f : 0.0f;
        g_maskf[m]  = mv;
        out_mask[m] = mv;
    }
}

// ---------------------------------------------------------------------------
// Fused gated dilated conv layer as SGEMM.
//   h[m, n] = bias[n] + sum_{tap,k} x[b, s+(tap-1)*dil, k] * W[tap,k,n]
//   g  = sigmoid(h[:, :256]);  hv = h[:, 256:]
//   y  = (RES ? x*(1-g)+hv*g : hv*g) * mask
// Tile: BM=64 rows, BN=64 of the 256 output channels (gate+value both
// accumulated), BK=32, 256 threads, 4x4x2 fragments per thread.
// ---------------------------------------------------------------------------
template <int CIN, int RES>
__global__ __launch_bounds__(256)
void conv_kernel(const float* __restrict__ x,
                 const float* __restrict__ W,
                 const float* __restrict__ bias,
                 float* __restrict__ y,
                 int dil) {
    __shared__ float xs[64 * 32];
    __shared__ float wgs[32 * 64];
    __shared__ float wvs[32 * 64];

    const int tid = threadIdx.x;
    const int m0  = blockIdx.x * 64;
    const int n0  = blockIdx.y * 64;
    const int b   = m0 >> 9;
    const int s0  = m0 & 511;
    const int tx  = tid & 15;
    const int ty  = tid >> 4;

    // load maps
    const int lr = tid >> 2;          // xs row (0..63)
    const int lc = (tid & 3) * 8;     // xs col start
    const int wr = tid >> 3;          // w row (0..31)
    const int wc = (tid & 7) * 8;     // w col start

    float accg[4][4];
    float accv[4][4];
#pragma unroll
    for (int i = 0; i < 4; ++i)
#pragma unroll
        for (int j = 0; j < 4; ++j) { accg[i][j] = 0.f; accv[i][j] = 0.f; }

    for (int tap = 0; tap < 3; ++tap) {
        const int off  = (tap - 1) * dil;
        const int srow = s0 + lr + off;
        const bool inb = (srow >= 0) && (srow < 512);
        const float* xrow = x + (size_t)(b * 512 + srow) * CIN;
        const float* Wt   = W + (size_t)tap * CIN * 512;

        for (int k0 = 0; k0 < CIN; k0 += 32) {
            // x tile
            if (inb) {
                float4 v0 = *(const float4*)(xrow + k0 + lc);
                float4 v1 = *(const float4*)(xrow + k0 + lc + 4);
                *(float4*)&xs[lr * 32 + lc]     = v0;
                *(float4*)&xs[lr * 32 + lc + 4] = v1;
            } else {
                float4 z = make_float4(0.f, 0.f, 0.f, 0.f);
                *(float4*)&xs[lr * 32 + lc]     = z;
                *(float4*)&xs[lr * 32 + lc + 4] = z;
            }
            // weight tiles (gate cols n0.., value cols n0+256..)
            const float* wrow = Wt + (size_t)(k0 + wr) * 512 + n0;
            *(float4*)&wgs[wr * 64 + wc]     = *(const float4*)(wrow + wc);
            *(float4*)&wgs[wr * 64 + wc + 4] = *(const float4*)(wrow + wc + 4);
            *(float4*)&wvs[wr * 64 + wc]     = *(const float4*)(wrow + 256 + wc);
            *(float4*)&wvs[wr * 64 + wc + 4] = *(const float4*)(wrow + 256 + wc + 4);
            __syncthreads();

#pragma unroll
            for (int kk = 0; kk < 32; ++kk) {
                float a[4];
#pragma unroll
                for (int i = 0; i < 4; ++i) a[i] = xs[(ty * 4 + i) * 32 + kk];
                float4 bg = *(float4*)&wgs[kk * 64 + tx * 4];
                float4 bv = *(float4*)&wvs[kk * 64 + tx * 4];
                float bgv[4] = {bg.x, bg.y, bg.z, bg.w};
                float bvv[4] = {bv.x, bv.y, bv.z, bv.w};
#pragma unroll
                for (int i = 0; i < 4; ++i)
#pragma unroll
                    for (int j = 0; j < 4; ++j) {
                        accg[i][j] = fmaf(a[i], bgv[j], accg[i][j]);
                        accv[i][j] = fmaf(a[i], bvv[j], accv[i][j]);
                    }
            }
            __syncthreads();
        }
    }

    // epilogue
#pragma unroll
    for (int i = 0; i < 4; ++i) {
        const int m = m0 + ty * 4 + i;
        const float mk = g_maskf[m];
        float xr[4] = {0.f, 0.f, 0.f, 0.f};
        if (RES) {
            float4 xv = *(const float4*)(x + (size_t)m * CIN + n0 + tx * 4);
            xr[0] = xv.x; xr[1] = xv.y; xr[2] = xv.z; xr[3] = xv.w;
        }
#pragma unroll
        for (int j = 0; j < 4; ++j) {
            const int c = n0 + tx * 4 + j;
            float g  = sigmoidf_(accg[i][j] + bias[c]);
            float hv = accv[i][j] + bias[c + 256];
            float o  = RES ? fmaf(g, hv - xr[j], xr[j]) : hv * g;
            y[(size_t)m * 256 + c] = o * mk;
        }
    }
}

// ---------------------------------------------------------------------------
// sub head: out[b, k, s] = sigmoid(x[m,:] . sub_w[:,k] + sub_b[k])
// one warp per row m
// ---------------------------------------------------------------------------
__global__ void sub_kernel(const float* __restrict__ x,
                           const float* __restrict__ sw,
                           const float* __restrict__ sb,
                           float* __restrict__ out) {
    int warp = threadIdx.x >> 5;
    int lane = threadIdx.x & 31;
    int m = blockIdx.x * 8 + warp;
    const float* xr = x + (size_t)m * 256;
    float a0 = 0.f, a1 = 0.f;
#pragma unroll
    for (int w = 0; w < 8; ++w) {
        int k = lane + w * 32;
        float xv = xr[k];
        a0 = fmaf(xv, sw[k * 2 + 0], a0);
        a1 = fmaf(xv, sw[k * 2 + 1], a1);
    }
#pragma unroll
    for (int o = 16; o; o >>= 1) {
        a0 += __shfl_xor_sync(0xffffffffu, a0, o);
        a1 += __shfl_xor_sync(0xffffffffu, a1, o);
    }
    if (lane == 0) {
        int b = m >> 9, s = m & 511;
        out[OFF_SUB + b * 1024 + s]       = sigmoidf_(a0 + sb[0]);
        out[OFF_SUB + b * 1024 + 512 + s] = sigmoidf_(a1 + sb[1]);
    }
}

// ---------------------------------------------------------------------------
// BN statistics + PO weight folding
// ---------------------------------------------------------------------------
__global__ void zero_sums_kernel() {
    int f = threadIdx.x;
    if (f < F3D) { g_sum[f] = 0.f; g_sumsq[f] = 0.f; }
}

__global__ void xstats_kernel(const float* __restrict__ x) {
    int t  = threadIdx.x;                // feature 0..255
    int r0 = blockIdx.x * 128;
    float s = 0.f, q = 0.f;
    for (int r = 0; r < 128; ++r) {
        float v = x[(size_t)(r0 + r) * 256 + t];
        s += v; q += v * v;
    }
    atomicAdd(&g_sum[t], s);
    atomicAdd(&g_sumsq[t], q);
}

__global__ void vec_kernel(const float* __restrict__ x,
                           const int* __restrict__ subloc) {
    int f = threadIdx.x;                 // 0..511
    int half = f >> 8;
    int fi = f & 255;
    float s = 0.f, q = 0.f;
    for (int b = 0; b < 64; ++b) {
        int loc = subloc[b * 2 + half];
        float v = x[(size_t)((b << 9) + loc) * 256 + fi];
        g_vec[b * 512 + f] = v;
        s += v; q += v * v;
    }
    g_sum[256 + f] = s;
    g_sumsq[256 + f] = q;
}

__global__ void finalize_kernel(const float* __restrict__ gamma,
                                const float* __restrict__ beta) {
    int f = threadIdx.x;
    if (f >= F3D) return;
    float n   = (f < 256) ? 32768.0f : 64.0f;
    float mu  = g_sum[f] / n;
    float var = g_sumsq[f] / n - mu * mu;
    float sc  = gamma[f] * rsqrtf(var + 0.001f);
    g_scale[f] = sc;
    g_shift[f] = beta[f] - mu * sc;
}

__global__ void weff_kernel(const float* __restrict__ po_w) {
    int idx = blockIdx.x * 256 + threadIdx.x;
    if (idx < F3D * P2) g_weff[idx] = po_w[idx] * g_scale[idx / P2];
}

__global__ void beff_kernel(const float* __restrict__ po_w,
                            const float* __restrict__ po_b) {
    int p = threadIdx.x;
    if (p >= P2) return;
    float acc = po_b[p];
    for (int f = 0; f < F3D; ++f) acc = fmaf(g_shift[f], po_w[f * P2 + p], acc);
    g_beff[p] = acc;
}

__global__ void cvec_kernel() {
    int b = blockIdx.x;
    int p = threadIdx.x;
    if (p >= P2) return;
    float acc = 0.f;
    for (int f = 0; f < 512; ++f)
        acc = fmaf(g_vec[b * 512 + f], g_weff[(256 + f) * P2 + p], acc);
    g_c[b * 128 + p] = acc;
}

// ---------------------------------------------------------------------------
// PO head: out[b, p, s] = sigmoid( x[m,:256] . w_eff[:256, p] + c[b,p] + b_eff[p] )
// 16 rows per block, 256 threads.
// ---------------------------------------------------------------------------
__global__ __launch_bounds__(256)
void po_kernel(const float* __restrict__ x, float* __restrict__ out) {
    __shared__ float xs[16 * 256];
    int m0 = blockIdx.x * 16;
    const float* xg = x + (size_t)m0 * 256;
#pragma unroll
    for (int v = 0; v < 4; ++v) {
        int off = threadIdx.x * 4 + v * 1024;
        *(float4*)&xs[off] = *(const float4*)(xg + off);
    }
    __syncthreads();

    int p  = threadIdx.x & 127;
    int rg = threadIdx.x >> 7;
    if (p < P2) {
        float acc[8];
#pragma unroll
        for (int i = 0; i < 8; ++i) acc[i] = 0.f;
        for (int k = 0; k < 256; ++k) {
            float wv = g_weff[k * P2 + p];
#pragma unroll
            for (int i = 0; i < 8; ++i)
                acc[i] = fmaf(xs[(rg + i * 2) * 256 + k], wv, acc[i]);
        }
        float be = g_beff[p];
#pragma unroll
        for (int i = 0; i < 8; ++i) {
            int m = m0 + rg + i * 2;
            int b = m >> 9, s = m & 511;
            out[OFF_PO + ((size_t)b * P2 + p) * 512 + s] =
                sigmoidf_(acc[i] + g_c[b * 128 + p] + be);
        }
    }
}

// ---------------------------------------------------------------------------
// kernel_launch
// ---------------------------------------------------------------------------
extern "C" void kernel_launch(void* const* d_in, const int* in_sizes, int n_in,
                              void* d_out, int out_size) {
    const int*   inputs   = (const int*)d_in[0];
    const int*   words    = (const int*)d_in[1];
    const int*   pos      = (const int*)d_in[2];
    const int*   subloc   = (const int*)d_in[3];
    const float* ctab     = (const float*)d_in[4];
    const float* wtab     = (const float*)d_in[5];
    const float* ptab     = (const float*)d_in[6];
    const float* conv_w1  = (const float*)d_in[7];
    const float* conv_b1  = (const float*)d_in[8];
    const float* conv_w   = (const float*)d_in[9];
    const float* conv_b   = (const float*)d_in[10];
    const float* sub_w    = (const float*)d_in[11];
    const float* sub_b    = (const float*)d_in[12];
    const float* po_w     = (const float*)d_in[13];
    const float* po_b     = (const float*)d_in[14];
    const float* bn_gamma = (const float*)d_in[15];
    const float* bn_beta  = (const float*)d_in[16];
    float* out = (float*)d_out;

    float *embed = nullptr, *xa = nullptr, *xb = nullptr;
    cudaGetSymbolAddress((void**)&embed, g_embed);
    cudaGetSymbolAddress((void**)&xa, g_xa);
    cudaGetSymbolAddress((void**)&xb, g_xb);

    // 1) embedding + mask
    embed_kernel<<<Mrows, 128>>>(inputs, words, pos, ctab, wtab, ptab,
                                 out + OFF_MASK);

    // 2) conv layers
    dim3 cgrid(Mrows / 64, 4);
    conv_kernel<512, 0><<<cgrid, 256>>>(embed, conv_w1, conv_b1, xa, 1);

    const int dils[11] = {2, 5, 1, 2, 5, 1, 2, 5, 1, 1, 1};
    float* bufs[2] = {xa, xb};
    float* cur = xa;
    for (int i = 0; i < 11; ++i) {
        float* nxt = bufs[(i + 1) & 1];
        conv_kernel<256, 1><<<cgrid, 256>>>(
            cur, conv_w + (size_t)i * 3 * 256 * 512, conv_b + i * 512, nxt,
            dils[i]);
        cur = nxt;
    }

    // 3) sub head
    sub_kernel<<<Mrows / 8, 256>>>(cur, sub_w, sub_b, out);

    // 4) BN stats + folded PO head
    zero_sums_kernel<<<1, F3D>>>();
    xstats_kernel<<<256, 256>>>(cur);
    vec_kernel<<<1, 512>>>(cur, subloc);
    finalize_kernel<<<1, F3D>>>(bn_gamma, bn_beta);
    weff_kernel<<<(F3D * P2 + 255) / 256, 256>>>(po_w);
    beff_kernel<<<1, 128>>>(po_w, po_b);
    cvec_kernel<<<Bsz, 128>>>();
    po_kernel<<<Mrows / 16, 256>>>(cur, out);

    (void)in_sizes; (void)n_in; (void)out_size;
}

// round 14
// speedup vs baseline: 3.2885x; 3.2885x over previous
#include <cuda_runtime.h>
#include <cstdint>

// ---------------------------------------------------------------------------
// Problem constants
// ---------------------------------------------------------------------------
#define Bsz   64
#define Ssz   512
#define Mrows (Bsz * Ssz)          // 32768
#define P2    100                  // 2*P
#define F3D   768                  // 3*D

#define OFF_SUB  0
#define OFF_PO   (Bsz * 2 * Ssz)                 // 65536
#define OFF_MASK (OFF_PO + Bsz * P2 * Ssz)       // 3342336

// ---------------------------------------------------------------------------
// Scratch (static __device__ globals; no allocation allowed)
// ---------------------------------------------------------------------------
__device__ float g_embed[(size_t)Mrows * 512];   // 64 MB
__device__ float g_xa[(size_t)Mrows * 256];      // 32 MB
__device__ float g_xb[(size_t)Mrows * 256];      // 32 MB
__device__ float g_maskf[Mrows];
__device__ float g_wt1[3 * 512 * 512];           // conv1 weights transposed [tap][n][k]
__device__ float g_wt[11 * 3 * 512 * 256];       // conv weights transposed
__device__ float g_vec[Bsz * 512];
__device__ float g_sum[F3D];
__device__ float g_sumsq[F3D];
__device__ float g_scale[F3D];
__device__ float g_shift[F3D];
__device__ float g_weff[F3D * P2];
__device__ float g_beff[128];
__device__ float g_c[Bsz * 128];

__device__ __forceinline__ float sigmoidf_(float x) {
    return 1.0f / (1.0f + __expf(-x));
}

__device__ __forceinline__ float tf32r(float x) {
    uint32_t u;
    asm("cvt.rna.tf32.f32 %0, %1;" : "=r"(u) : "f"(x));
    return __uint_as_float(u);
}

__device__ __forceinline__ void mma_tf32(float d[4], const uint32_t a[4],
                                         const uint32_t b[2]) {
    asm volatile(
        "mma.sync.aligned.m16n8k8.row.col.f32.tf32.tf32.f32 "
        "{%0,%1,%2,%3}, {%4,%5,%6,%7}, {%8,%9}, {%0,%1,%2,%3};"
        : "+f"(d[0]), "+f"(d[1]), "+f"(d[2]), "+f"(d[3])
        : "r"(a[0]), "r"(a[1]), "r"(a[2]), "r"(a[3]), "r"(b[0]), "r"(b[1]));
}

// ---------------------------------------------------------------------------
// Embedding + mask
// ---------------------------------------------------------------------------
__global__ void embed_kernel(const int* __restrict__ inputs,
                             const int* __restrict__ words,
                             const int* __restrict__ pos,
                             const float* __restrict__ ctab,
                             const float* __restrict__ wtab,
                             const float* __restrict__ ptab,
                             float* __restrict__ out_mask) {
    int m = blockIdx.x;
    int c = threadIdx.x * 4;
    int ci = inputs[m];
    int wi = words[m];
    int pi = pos[m];
    float4 e;
    if (c < 256) {
        e = *(const float4*)(ctab + (size_t)ci * 256 + c);
    } else {
        e = *(const float4*)(wtab + (size_t)wi * 256 + (c - 256));
    }
    float4 pv = *(const float4*)(ptab + (size_t)pi * 512 + c);
    e.x += pv.x; e.y += pv.y; e.z += pv.z; e.w += pv.w;
    *(float4*)(g_embed + (size_t)m * 512 + c) = e;
    if (threadIdx.x == 0) {
        float mv = (ci != 0) ? 1.0f : 0.0f;
        g_maskf[m]  = mv;
        out_mask[m] = mv;
    }
}

// ---------------------------------------------------------------------------
// Weight transpose: src[z][K][N] -> dst[z][N][K], with tf32 rounding
// ---------------------------------------------------------------------------
__global__ void transpose_kernel(const float* __restrict__ src,
                                 float* __restrict__ dst, int K, int N) {
    __shared__ float t[32][33];
    const float* s = src + (size_t)blockIdx.z * K * N;
    float* d = dst + (size_t)blockIdx.z * K * N;
    int k0 = blockIdx.x * 32, n0 = blockIdx.y * 32;
    int tx = threadIdx.x, ty = threadIdx.y;
#pragma unroll
    for (int i = 0; i < 32; i += 8)
        t[ty + i][tx] = s[(size_t)(k0 + ty + i) * N + n0 + tx];
    __syncthreads();
#pragma unroll
    for (int i = 0; i < 32; i += 8)
        d[(size_t)(n0 + ty + i) * K + k0 + tx] = tf32r(t[tx][ty + i]);
}

// ---------------------------------------------------------------------------
// Gated dilated conv layer on tf32 mma.sync (arch-agnostic PTX).
// Block: 128 rows x 64 output channels. In-block col 2j = gate(ch n0+j),
// col 2j+1 = value(ch n0+j): mma accumulator pairs (c0,c1)/(c2,c3) hold the
// (gate,value) pair for one output channel -> fused gating epilogue.
// 8 warps as 2(m) x 4(n); warp tile 64x32; K-chunk 32 (4 k8 mma steps).
// Smem strides padded to 36 floats -> conflict-free fragment loads.
// ---------------------------------------------------------------------------
template <int CIN, int RES>
__global__ __launch_bounds__(256, 2)
void tconv_kernel(const float* __restrict__ x,
                  const float* __restrict__ wt,     // [3][512][CIN] tf32-rounded
                  const float* __restrict__ bias,   // [512]
                  float* __restrict__ y,
                  int dil) {
    __shared__ float As[128 * 36];
    __shared__ float Bs[128 * 36];
    __shared__ float bias_s[512];

    const int tid  = threadIdx.x;
    const int wid  = tid >> 5;
    const int lane = tid & 31;
    const int l4   = lane & 3;
    const int ld4  = lane >> 2;
    const int m0   = blockIdx.x * 128;
    const int n0   = blockIdx.y * 64;
    const int b    = m0 >> 9;
    const int s0   = m0 & 511;

    const int wm = (wid & 1) * 64;        // warp row offset
    const int wn = (wid >> 1) * 32;       // warp col offset (in-block, 0..127)

    if (tid < 128) ((float4*)bias_s)[tid] = ((const float4*)bias)[tid];

    float d[4][4][4];
#pragma unroll
    for (int mi = 0; mi < 4; ++mi)
#pragma unroll
        for (int ni = 0; ni < 4; ++ni)
#pragma unroll
            for (int r = 0; r < 4; ++r) d[mi][ni][r] = 0.f;

    const int NCK = CIN / 32;
    const int NC  = 3 * NCK;
    const float* xb = x + (size_t)b * 512 * CIN;

    // staging maps: idx = it*256+tid, row/n = idx>>3 (0..127), kg = idx&7
#pragma unroll 1
    for (int c = 0; c < NC; ++c) {
        const int tap = c / NCK;
        const int k0  = (c - tap * NCK) * 32;
        const int off = (tap - 1) * dil;

        __syncthreads();
        // A tile: 128 rows x 32 k, tf32-rounded, OOB rows zero
#pragma unroll
        for (int it = 0; it < 4; ++it) {
            int idx = it * 256 + tid;
            int row = idx >> 3, kg = idx & 7;
            int srow = s0 + row + off;
            float4 v = make_float4(0.f, 0.f, 0.f, 0.f);
            if (srow >= 0 && srow < 512)
                v = *(const float4*)(xb + (size_t)srow * CIN + k0 + kg * 4);
            v.x = tf32r(v.x); v.y = tf32r(v.y);
            v.z = tf32r(v.z); v.w = tf32r(v.w);
            float* p = &As[row * 36 + kg * 4];
            p[0] = v.x; p[1] = v.y; p[2] = v.z; p[3] = v.w;
        }
        // B tile: 128 n-rows (gate/value interleaved) x 32 k
        const float* wtp = wt + (size_t)tap * 512 * CIN + k0;
#pragma unroll
        for (int it = 0; it < 4; ++it) {
            int idx = it * 256 + tid;
            int n = idx >> 3, kg = idx & 7;
            int j = n >> 1;
            int col = (n & 1) ? (n0 + 256 + j) : (n0 + j);
            float4 v = *(const float4*)(wtp + (size_t)col * CIN + kg * 4);
            float* p = &Bs[n * 36 + kg * 4];
            p[0] = v.x; p[1] = v.y; p[2] = v.z; p[3] = v.w;
        }
        __syncthreads();

#pragma unroll
        for (int kk = 0; kk < 4; ++kk) {
            const int kb = kk * 8;
            uint32_t a[4][4];
#pragma unroll
            for (int mi = 0; mi < 4; ++mi) {
                const float* ap = &As[(wm + mi * 16 + ld4) * 36 + kb + l4];
                a[mi][0] = __float_as_uint(ap[0]);
                a[mi][1] = __float_as_uint(ap[8 * 36]);
                a[mi][2] = __float_as_uint(ap[4]);
                a[mi][3] = __float_as_uint(ap[8 * 36 + 4]);
            }
            uint32_t bf[4][2];
#pragma unroll
            for (int ni = 0; ni < 4; ++ni) {
                const float* bp = &Bs[(wn + ni * 8 + ld4) * 36 + kb + l4];
                bf[ni][0] = __float_as_uint(bp[0]);
                bf[ni][1] = __float_as_uint(bp[4]);
            }
#pragma unroll
            for (int mi = 0; mi < 4; ++mi)
#pragma unroll
                for (int ni = 0; ni < 4; ++ni)
                    mma_tf32(d[mi][ni], a[mi], bf[ni]);
        }
    }

    // Epilogue: (c0,c1) = (gate,value) of one channel at row; (c2,c3) at row+8
#pragma unroll
    for (int mi = 0; mi < 4; ++mi) {
        const int row0 = m0 + wm + mi * 16 + ld4;
        const int row1 = row0 + 8;
        const float mk0 = g_maskf[row0];
        const float mk1 = g_maskf[row1];
        const float* xr0 = x + (size_t)row0 * CIN;
        const float* xr1 = x + (size_t)row1 * CIN;
#pragma unroll
        for (int ni = 0; ni < 4; ++ni) {
            const int co = n0 + (wn >> 1) + ni * 4 + l4;   // output channel
            const float bg = bias_s[co];
            const float bv = bias_s[co + 256];
            float g0 = sigmoidf_(d[mi][ni][0] + bg);
            float h0 = d[mi][ni][1] + bv;
            float g1 = sigmoidf_(d[mi][ni][2] + bg);
            float h1 = d[mi][ni][3] + bv;
            float o0, o1;
            if (RES) {
                float x0 = xr0[co], x1 = xr1[co];
                o0 = fmaf(g0, h0 - x0, x0);
                o1 = fmaf(g1, h1 - x1, x1);
            } else {
                o0 = g0 * h0;
                o1 = g1 * h1;
            }
            y[(size_t)row0 * 256 + co] = o0 * mk0;
            y[(size_t)row1 * 256 + co] = o1 * mk1;
        }
    }
}

// ---------------------------------------------------------------------------
// sub head
// ---------------------------------------------------------------------------
__global__ void sub_kernel(const float* __restrict__ x,
                           const float* __restrict__ sw,
                           const float* __restrict__ sb,
                           float* __restrict__ out) {
    int warp = threadIdx.x >> 5;
    int lane = threadIdx.x & 31;
    int m = blockIdx.x * 8 + warp;
    const float* xr = x + (size_t)m * 256;
    float a0 = 0.f, a1 = 0.f;
#pragma unroll
    for (int w = 0; w < 8; ++w) {
        int k = lane + w * 32;
        float xv = xr[k];
        a0 = fmaf(xv, sw[k * 2 + 0], a0);
        a1 = fmaf(xv, sw[k * 2 + 1], a1);
    }
#pragma unroll
    for (int o = 16; o; o >>= 1) {
        a0 += __shfl_xor_sync(0xffffffffu, a0, o);
        a1 += __shfl_xor_sync(0xffffffffu, a1, o);
    }
    if (lane == 0) {
        int b = m >> 9, s = m & 511;
        out[OFF_SUB + b * 1024 + s]       = sigmoidf_(a0 + sb[0]);
        out[OFF_SUB + b * 1024 + 512 + s] = sigmoidf_(a1 + sb[1]);
    }
}

// ---------------------------------------------------------------------------
// BN statistics + PO weight folding
// ---------------------------------------------------------------------------
__global__ void zero_sums_kernel() {
    int f = threadIdx.x;
    if (f < F3D) { g_sum[f] = 0.f; g_sumsq[f] = 0.f; }
}

__global__ void xstats_kernel(const float* __restrict__ x) {
    int t  = threadIdx.x;
    int r0 = blockIdx.x * 128;
    float s = 0.f, q = 0.f;
    for (int r = 0; r < 128; ++r) {
        float v = x[(size_t)(r0 + r) * 256 + t];
        s += v; q += v * v;
    }
    atomicAdd(&g_sum[t], s);
    atomicAdd(&g_sumsq[t], q);
}

__global__ void vec_kernel(const float* __restrict__ x,
                           const int* __restrict__ subloc) {
    int f = threadIdx.x;
    int half = f >> 8;
    int fi = f & 255;
    float s = 0.f, q = 0.f;
    for (int b = 0; b < 64; ++b) {
        int loc = subloc[b * 2 + half];
        float v = x[(size_t)((b << 9) + loc) * 256 + fi];
        g_vec[b * 512 + f] = v;
        s += v; q += v * v;
    }
    g_sum[256 + f] = s;
    g_sumsq[256 + f] = q;
}

__global__ void finalize_kernel(const float* __restrict__ gamma,
                                const float* __restrict__ beta) {
    int f = threadIdx.x;
    if (f >= F3D) return;
    float n   = (f < 256) ? 32768.0f : 64.0f;
    float mu  = g_sum[f] / n;
    float var = g_sumsq[f] / n - mu * mu;
    float sc  = gamma[f] * rsqrtf(var + 0.001f);
    g_scale[f] = sc;
    g_shift[f] = beta[f] - mu * sc;
}

__global__ void weff_kernel(const float* __restrict__ po_w) {
    int idx = blockIdx.x * 256 + threadIdx.x;
    if (idx < F3D * P2) g_weff[idx] = po_w[idx] * g_scale[idx / P2];
}

__global__ void beff_kernel(const float* __restrict__ po_w,
                            const float* __restrict__ po_b) {
    int p = threadIdx.x;
    if (p >= P2) return;
    float acc = po_b[p];
    for (int f = 0; f < F3D; ++f) acc = fmaf(g_shift[f], po_w[f * P2 + p], acc);
    g_beff[p] = acc;
}

__global__ void cvec_kernel() {
    int b = blockIdx.x;
    int p = threadIdx.x;
    if (p >= P2) return;
    float acc = 0.f;
    for (int f = 0; f < 512; ++f)
        acc = fmaf(g_vec[b * 512 + f], g_weff[(256 + f) * P2 + p], acc);
    g_c[b * 128 + p] = acc;
}

__global__ __launch_bounds__(256)
void po_kernel(const float* __restrict__ x, float* __restrict__ out) {
    __shared__ float xs[16 * 256];
    int m0 = blockIdx.x * 16;
    const float* xg = x + (size_t)m0 * 256;
#pragma unroll
    for (int v = 0; v < 4; ++v) {
        int off = threadIdx.x * 4 + v * 1024;
        *(float4*)&xs[off] = *(const float4*)(xg + off);
    }
    __syncthreads();

    int p  = threadIdx.x & 127;
    int rg = threadIdx.x >> 7;
    if (p < P2) {
        float acc[8];
#pragma unroll
        for (int i = 0; i < 8; ++i) acc[i] = 0.f;
        for (int k = 0; k < 256; ++k) {
            float wv = g_weff[k * P2 + p];
#pragma unroll
            for (int i = 0; i < 8; ++i)
                acc[i] = fmaf(xs[(rg + i * 2) * 256 + k], wv, acc[i]);
        }
        float be = g_beff[p];
#pragma unroll
        for (int i = 0; i < 8; ++i) {
            int m = m0 + rg + i * 2;
            int b = m >> 9, s = m & 511;
            out[OFF_PO + ((size_t)b * P2 + p) * 512 + s] =
                sigmoidf_(acc[i] + g_c[b * 128 + p] + be);
        }
    }
}

// ---------------------------------------------------------------------------
// kernel_launch
// ---------------------------------------------------------------------------
extern "C" void kernel_launch(void* const* d_in, const int* in_sizes, int n_in,
                              void* d_out, int out_size) {
    const int*   inputs   = (const int*)d_in[0];
    const int*   words    = (const int*)d_in[1];
    const int*   pos      = (const int*)d_in[2];
    const int*   subloc   = (const int*)d_in[3];
    const float* ctab     = (const float*)d_in[4];
    const float* wtab     = (const float*)d_in[5];
    const float* ptab     = (const float*)d_in[6];
    const float* conv_w1  = (const float*)d_in[7];
    const float* conv_b1  = (const float*)d_in[8];
    const float* conv_w   = (const float*)d_in[9];
    const float* conv_b   = (const float*)d_in[10];
    const float* sub_w    = (const float*)d_in[11];
    const float* sub_b    = (const float*)d_in[12];
    const float* po_w     = (const float*)d_in[13];
    const float* po_b     = (const float*)d_in[14];
    const float* bn_gamma = (const float*)d_in[15];
    const float* bn_beta  = (const float*)d_in[16];
    float* out = (float*)d_out;

    float *embed = nullptr, *xa = nullptr, *xb = nullptr;
    float *wt1 = nullptr, *wt = nullptr;
    cudaGetSymbolAddress((void**)&embed, g_embed);
    cudaGetSymbolAddress((void**)&xa, g_xa);
    cudaGetSymbolAddress((void**)&xb, g_xb);
    cudaGetSymbolAddress((void**)&wt1, g_wt1);
    cudaGetSymbolAddress((void**)&wt, g_wt);

    // 0) transpose weights to [n][k] (tf32-rounded), once per launch
    {
        dim3 blk(32, 8);
        dim3 g1(16, 16, 3);
        transpose_kernel<<<g1, blk>>>(conv_w1, wt1, 512, 512);
        dim3 g2(8, 16, 33);
        transpose_kernel<<<g2, blk>>>(conv_w, wt, 256, 512);
    }

    // 1) embedding + mask
    embed_kernel<<<Mrows, 128>>>(inputs, words, pos, ctab, wtab, ptab,
                                 out + OFF_MASK);

    // 2) conv layers on tf32 mma.sync
    dim3 cgrid(Mrows / 128, 4);
    tconv_kernel<512, 0><<<cgrid, 256>>>(embed, wt1, conv_b1, xa, 1);
    const int dils[11] = {2, 5, 1, 2, 5, 1, 2, 5, 1, 1, 1};
    float* bufs[2] = {xa, xb};
    float* cur = xa;
    for (int i = 0; i < 11; ++i) {
        float* nxt = bufs[(i + 1) & 1];
        tconv_kernel<256, 1><<<cgrid, 256>>>(
            cur, wt + (size_t)i * 3 * 512 * 256, conv_b + i * 512, nxt,
            dils[i]);
        cur = nxt;
    }

    // 3) sub head
    sub_kernel<<<Mrows / 8, 256>>>(cur, sub_w, sub_b, out);

    // 4) BN stats + folded PO head
    zero_sums_kernel<<<1, F3D>>>();
    xstats_kernel<<<256, 256>>>(cur);
    vec_kernel<<<1, 512>>>(cur, subloc);
    finalize_kernel<<<1, F3D>>>(bn_gamma, bn_beta);
    weff_kernel<<<(F3D * P2 + 255) / 256, 256>>>(po_w);
    beff_kernel<<<1, 128>>>(po_w, po_b);
    cvec_kernel<<<Bsz, 128>>>();
    po_kernel<<<Mrows / 16, 256>>>(cur, out);

    (void)in_sizes; (void)n_in; (void)out_size;
}

// round 15
// speedup vs baseline: 3.2911x; 1.0008x over previous
#include <cuda_runtime.h>
#include <cstdint>

// ---------------------------------------------------------------------------
// Problem constants
// ---------------------------------------------------------------------------
#define Bsz   64
#define Ssz   512
#define Mrows (Bsz * Ssz)          // 32768
#define P2    100                  // 2*P
#define F3D   768                  // 3*D

#define OFF_SUB  0
#define OFF_PO   (Bsz * 2 * Ssz)                 // 65536
#define OFF_MASK (OFF_PO + Bsz * P2 * Ssz)       // 3342336

// ---------------------------------------------------------------------------
// Scratch (static __device__ globals; no allocation allowed)
// ---------------------------------------------------------------------------
__device__ float g_embed[(size_t)Mrows * 512];   // 64 MB
__device__ float g_xa[(size_t)Mrows * 256];      // 32 MB
__device__ float g_xb[(size_t)Mrows * 256];      // 32 MB
__device__ float g_maskf[Mrows];
__device__ float g_wt1[3 * 512 * 512];           // conv1 weights transposed [tap][n][k]
__device__ float g_wt[11 * 3 * 512 * 256];       // conv weights transposed
__device__ float g_vec[Bsz * 512];
__device__ float g_sum[F3D];
__device__ float g_sumsq[F3D];
__device__ float g_scale[F3D];
__device__ float g_shift[F3D];
__device__ float g_weff[F3D * P2];
__device__ float g_beff[128];
__device__ float g_c[Bsz * 128];

__device__ __forceinline__ float sigmoidf_(float x) {
    return 1.0f / (1.0f + __expf(-x));
}

__device__ __forceinline__ float tf32r(float x) {
    uint32_t u;
    asm("cvt.rna.tf32.f32 %0, %1;" : "=r"(u) : "f"(x));
    return __uint_as_float(u);
}

__device__ __forceinline__ void mma_tf32(float d[4], const uint32_t a[4],
                                         const uint32_t b[2]) {
    asm volatile(
        "mma.sync.aligned.m16n8k8.row.col.f32.tf32.tf32.f32 "
        "{%0,%1,%2,%3}, {%4,%5,%6,%7}, {%8,%9}, {%0,%1,%2,%3};"
        : "+f"(d[0]), "+f"(d[1]), "+f"(d[2]), "+f"(d[3])
        : "r"(a[0]), "r"(a[1]), "r"(a[2]), "r"(a[3]), "r"(b[0]), "r"(b[1]));
}

// ---------------------------------------------------------------------------
// Embedding + mask
// ---------------------------------------------------------------------------
__global__ void embed_kernel(const int* __restrict__ inputs,
                             const int* __restrict__ words,
                             const int* __restrict__ pos,
                             const float* __restrict__ ctab,
                             const float* __restrict__ wtab,
                             const float* __restrict__ ptab,
                             float* __restrict__ out_mask) {
    int m = blockIdx.x;
    int c = threadIdx.x * 4;
    int ci = inputs[m];
    int wi = words[m];
    int pi = pos[m];
    float4 e;
    if (c < 256) {
        e = *(const float4*)(ctab + (size_t)ci * 256 + c);
    } else {
        e = *(const float4*)(wtab + (size_t)wi * 256 + (c - 256));
    }
    float4 pv = *(const float4*)(ptab + (size_t)pi * 512 + c);
    e.x += pv.x; e.y += pv.y; e.z += pv.z; e.w += pv.w;
    *(float4*)(g_embed + (size_t)m * 512 + c) = e;
    if (threadIdx.x == 0) {
        float mv = (ci != 0) ? 1.0f : 0.0f;
        g_maskf[m]  = mv;
        out_mask[m] = mv;
    }
}

// ---------------------------------------------------------------------------
// Weight transpose: src[z][K][N] -> dst[z][N][K], with tf32 rounding
// ---------------------------------------------------------------------------
__global__ void transpose_kernel(const float* __restrict__ src,
                                 float* __restrict__ dst, int K, int N) {
    __shared__ float t[32][33];
    const float* s = src + (size_t)blockIdx.z * K * N;
    float* d = dst + (size_t)blockIdx.z * K * N;
    int k0 = blockIdx.x * 32, n0 = blockIdx.y * 32;
    int tx = threadIdx.x, ty = threadIdx.y;
#pragma unroll
    for (int i = 0; i < 32; i += 8)
        t[ty + i][tx] = s[(size_t)(k0 + ty + i) * N + n0 + tx];
    __syncthreads();
#pragma unroll
    for (int i = 0; i < 32; i += 8)
        d[(size_t)(n0 + ty + i) * K + k0 + tx] = tf32r(t[tx][ty + i]);
}

// ---------------------------------------------------------------------------
// Gated dilated conv layer on tf32 mma.sync (arch-agnostic PTX).
// Block: 128 rows x 64 output channels. In-block col 2j = gate(ch n0+j),
// col 2j+1 = value(ch n0+j): mma accumulator pairs (c0,c1)/(c2,c3) hold the
// (gate,value) pair for one output channel -> fused gating epilogue.
// 8 warps as 2(m) x 4(n); warp tile 64x32; K-chunk 32 (4 k8 mma steps).
// Smem strides padded to 36 floats -> conflict-free fragment loads.
// ---------------------------------------------------------------------------
template <int CIN, int RES>
__global__ __launch_bounds__(256, 2)
void tconv_kernel(const float* __restrict__ x,
                  const float* __restrict__ wt,     // [3][512][CIN] tf32-rounded
                  const float* __restrict__ bias,   // [512]
                  float* __restrict__ y,
                  int dil) {
    __shared__ float As[128 * 36];
    __shared__ float Bs[128 * 36];
    __shared__ float bias_s[512];

    const int tid  = threadIdx.x;
    const int wid  = tid >> 5;
    const int lane = tid & 31;
    const int l4   = lane & 3;
    const int ld4  = lane >> 2;
    const int m0   = blockIdx.x * 128;
    const int n0   = blockIdx.y * 64;
    const int b    = m0 >> 9;
    const int s0   = m0 & 511;

    const int wm = (wid & 1) * 64;        // warp row offset
    const int wn = (wid >> 1) * 32;       // warp col offset (in-block, 0..127)

    if (tid < 128) ((float4*)bias_s)[tid] = ((const float4*)bias)[tid];

    float d[4][4][4];
#pragma unroll
    for (int mi = 0; mi < 4; ++mi)
#pragma unroll
        for (int ni = 0; ni < 4; ++ni)
#pragma unroll
            for (int r = 0; r < 4; ++r) d[mi][ni][r] = 0.f;

    const int NCK = CIN / 32;
    const int NC  = 3 * NCK;
    const float* xb = x + (size_t)b * 512 * CIN;

    // staging maps: idx = it*256+tid, row/n = idx>>3 (0..127), kg = idx&7
#pragma unroll 1
    for (int c = 0; c < NC; ++c) {
        const int tap = c / NCK;
        const int k0  = (c - tap * NCK) * 32;
        const int off = (tap - 1) * dil;

        __syncthreads();
        // A tile: 128 rows x 32 k, tf32-rounded, OOB rows zero
#pragma unroll
        for (int it = 0; it < 4; ++it) {
            int idx = it * 256 + tid;
            int row = idx >> 3, kg = idx & 7;
            int srow = s0 + row + off;
            float4 v = make_float4(0.f, 0.f, 0.f, 0.f);
            if (srow >= 0 && srow < 512)
                v = *(const float4*)(xb + (size_t)srow * CIN + k0 + kg * 4);
            v.x = tf32r(v.x); v.y = tf32r(v.y);
            v.z = tf32r(v.z); v.w = tf32r(v.w);
            float* p = &As[row * 36 + kg * 4];
            p[0] = v.x; p[1] = v.y; p[2] = v.z; p[3] = v.w;
        }
        // B tile: 128 n-rows (gate/value interleaved) x 32 k
        const float* wtp = wt + (size_t)tap * 512 * CIN + k0;
#pragma unroll
        for (int it = 0; it < 4; ++it) {
            int idx = it * 256 + tid;
            int n = idx >> 3, kg = idx & 7;
            int j = n >> 1;
            int col = (n & 1) ? (n0 + 256 + j) : (n0 + j);
            float4 v = *(const float4*)(wtp + (size_t)col * CIN + kg * 4);
            float* p = &Bs[n * 36 + kg * 4];
            p[0] = v.x; p[1] = v.y; p[2] = v.z; p[3] = v.w;
        }
        __syncthreads();

#pragma unroll
        for (int kk = 0; kk < 4; ++kk) {
            const int kb = kk * 8;
            uint32_t a[4][4];
#pragma unroll
            for (int mi = 0; mi < 4; ++mi) {
                const float* ap = &As[(wm + mi * 16 + ld4) * 36 + kb + l4];
                a[mi][0] = __float_as_uint(ap[0]);
                a[mi][1] = __float_as_uint(ap[8 * 36]);
                a[mi][2] = __float_as_uint(ap[4]);
                a[mi][3] = __float_as_uint(ap[8 * 36 + 4]);
            }
            uint32_t bf[4][2];
#pragma unroll
            for (int ni = 0; ni < 4; ++ni) {
                const float* bp = &Bs[(wn + ni * 8 + ld4) * 36 + kb + l4];
                bf[ni][0] = __float_as_uint(bp[0]);
                bf[ni][1] = __float_as_uint(bp[4]);
            }
#pragma unroll
            for (int mi = 0; mi < 4; ++mi)
#pragma unroll
                for (int ni = 0; ni < 4; ++ni)
                    mma_tf32(d[mi][ni], a[mi], bf[ni]);
        }
    }

    // Epilogue: (c0,c1) = (gate,value) of one channel at row; (c2,c3) at row+8
#pragma unroll
    for (int mi = 0; mi < 4; ++mi) {
        const int row0 = m0 + wm + mi * 16 + ld4;
        const int row1 = row0 + 8;
        const float mk0 = g_maskf[row0];
        const float mk1 = g_maskf[row1];
        const float* xr0 = x + (size_t)row0 * CIN;
        const float* xr1 = x + (size_t)row1 * CIN;
#pragma unroll
        for (int ni = 0; ni < 4; ++ni) {
            const int co = n0 + (wn >> 1) + ni * 4 + l4;   // output channel
            const float bg = bias_s[co];
            const float bv = bias_s[co + 256];
            float g0 = sigmoidf_(d[mi][ni][0] + bg);
            float h0 = d[mi][ni][1] + bv;
            float g1 = sigmoidf_(d[mi][ni][2] + bg);
            float h1 = d[mi][ni][3] + bv;
            float o0, o1;
            if (RES) {
                float x0 = xr0[co], x1 = xr1[co];
                o0 = fmaf(g0, h0 - x0, x0);
                o1 = fmaf(g1, h1 - x1, x1);
            } else {
                o0 = g0 * h0;
                o1 = g1 * h1;
            }
            y[(size_t)row0 * 256 + co] = o0 * mk0;
            y[(size_t)row1 * 256 + co] = o1 * mk1;
        }
    }
}

// ---------------------------------------------------------------------------
// sub head
// ---------------------------------------------------------------------------
__global__ void sub_kernel(const float* __restrict__ x,
                           const float* __restrict__ sw,
                           const float* __restrict__ sb,
                           float* __restrict__ out) {
    int warp = threadIdx.x >> 5;
    int lane = threadIdx.x & 31;
    int m = blockIdx.x * 8 + warp;
    const float* xr = x + (size_t)m * 256;
    float a0 = 0.f, a1 = 0.f;
#pragma unroll
    for (int w = 0; w < 8; ++w) {
        int k = lane + w * 32;
        float xv = xr[k];
        a0 = fmaf(xv, sw[k * 2 + 0], a0);
        a1 = fmaf(xv, sw[k * 2 + 1], a1);
    }
#pragma unroll
    for (int o = 16; o; o >>= 1) {
        a0 += __shfl_xor_sync(0xffffffffu, a0, o);
        a1 += __shfl_xor_sync(0xffffffffu, a1, o);
    }
    if (lane == 0) {
        int b = m >> 9, s = m & 511;
        out[OFF_SUB + b * 1024 + s]       = sigmoidf_(a0 + sb[0]);
        out[OFF_SUB + b * 1024 + 512 + s] = sigmoidf_(a1 + sb[1]);
    }
}

// ---------------------------------------------------------------------------
// BN statistics + PO weight folding
// ---------------------------------------------------------------------------
__global__ void zero_sums_kernel() {
    int f = threadIdx.x;
    if (f < F3D) { g_sum[f] = 0.f; g_sumsq[f] = 0.f; }
}

__global__ void xstats_kernel(const float* __restrict__ x) {
    int t  = threadIdx.x;
    int r0 = blockIdx.x * 128;
    float s = 0.f, q = 0.f;
    for (int r = 0; r < 128; ++r) {
        float v = x[(size_t)(r0 + r) * 256 + t];
        s += v; q += v * v;
    }
    atomicAdd(&g_sum[t], s);
    atomicAdd(&g_sumsq[t], q);
}

__global__ void vec_kernel(const float* __restrict__ x,
                           const int* __restrict__ subloc) {
    int f = threadIdx.x;
    int half = f >> 8;
    int fi = f & 255;
    float s = 0.f, q = 0.f;
    for (int b = 0; b < 64; ++b) {
        int loc = subloc[b * 2 + half];
        float v = x[(size_t)((b << 9) + loc) * 256 + fi];
        g_vec[b * 512 + f] = v;
        s += v; q += v * v;
    }
    g_sum[256 + f] = s;
    g_sumsq[256 + f] = q;
}

__global__ void finalize_kernel(const float* __restrict__ gamma,
                                const float* __restrict__ beta) {
    int f = threadIdx.x;
    if (f >= F3D) return;
    float n   = (f < 256) ? 32768.0f : 64.0f;
    float mu  = g_sum[f] / n;
    float var = g_sumsq[f] / n - mu * mu;
    float sc  = gamma[f] * rsqrtf(var + 0.001f);
    g_scale[f] = sc;
    g_shift[f] = beta[f] - mu * sc;
}

__global__ void weff_kernel(const float* __restrict__ po_w) {
    int idx = blockIdx.x * 256 + threadIdx.x;
    if (idx < F3D * P2) g_weff[idx] = po_w[idx] * g_scale[idx / P2];
}

__global__ void beff_kernel(const float* __restrict__ po_w,
                            const float* __restrict__ po_b) {
    int p = threadIdx.x;
    if (p >= P2) return;
    float acc = po_b[p];
    for (int f = 0; f < F3D; ++f) acc = fmaf(g_shift[f], po_w[f * P2 + p], acc);
    g_beff[p] = acc;
}

__global__ void cvec_kernel() {
    int b = blockIdx.x;
    int p = threadIdx.x;
    if (p >= P2) return;
    float acc = 0.f;
    for (int f = 0; f < 512; ++f)
        acc = fmaf(g_vec[b * 512 + f], g_weff[(256 + f) * P2 + p], acc);
    g_c[b * 128 + p] = acc;
}

__global__ __launch_bounds__(256)
void po_kernel(const float* __restrict__ x, float* __restrict__ out) {
    __shared__ float xs[16 * 256];
    int m0 = blockIdx.x * 16;
    const float* xg = x + (size_t)m0 * 256;
#pragma unroll
    for (int v = 0; v < 4; ++v) {
        int off = threadIdx.x * 4 + v * 1024;
        *(float4*)&xs[off] = *(const float4*)(xg + off);
    }
    __syncthreads();

    int p  = threadIdx.x & 127;
    int rg = threadIdx.x >> 7;
    if (p < P2) {
        float acc[8];
#pragma unroll
        for (int i = 0; i < 8; ++i) acc[i] = 0.f;
        for (int k = 0; k < 256; ++k) {
            float wv = g_weff[k * P2 + p];
#pragma unroll
            for (int i = 0; i < 8; ++i)
                acc[i] = fmaf(xs[(rg + i * 2) * 256 + k], wv, acc[i]);
        }
        float be = g_beff[p];
#pragma unroll
        for (int i = 0; i < 8; ++i) {
            int m = m0 + rg + i * 2;
            int b = m >> 9, s = m & 511;
            out[OFF_PO + ((size_t)b * P2 + p) * 512 + s] =
                sigmoidf_(acc[i] + g_c[b * 128 + p] + be);
        }
    }
}

// ---------------------------------------------------------------------------
// kernel_launch
// ---------------------------------------------------------------------------
extern "C" void kernel_launch(void* const* d_in, const int* in_sizes, int n_in,
                              void* d_out, int out_size) {
    const int*   inputs   = (const int*)d_in[0];
    const int*   words    = (const int*)d_in[1];
    const int*   pos      = (const int*)d_in[2];
    const int*   subloc   = (const int*)d_in[3];
    const float* ctab     = (const float*)d_in[4];
    const float* wtab     = (const float*)d_in[5];
    const float* ptab     = (const float*)d_in[6];
    const float* conv_w1  = (const float*)d_in[7];
    const float* conv_b1  = (const float*)d_in[8];
    const float* conv_w   = (const float*)d_in[9];
    const float* conv_b   = (const float*)d_in[10];
    const float* sub_w    = (const float*)d_in[11];
    const float* sub_b    = (const float*)d_in[12];
    const float* po_w     = (const float*)d_in[13];
    const float* po_b     = (const float*)d_in[14];
    const float* bn_gamma = (const float*)d_in[15];
    const float* bn_beta  = (const float*)d_in[16];
    float* out = (float*)d_out;

    float *embed = nullptr, *xa = nullptr, *xb = nullptr;
    float *wt1 = nullptr, *wt = nullptr;
    cudaGetSymbolAddress((void**)&embed, g_embed);
    cudaGetSymbolAddress((void**)&xa, g_xa);
    cudaGetSymbolAddress((void**)&xb, g_xb);
    cudaGetSymbolAddress((void**)&wt1, g_wt1);
    cudaGetSymbolAddress((void**)&wt, g_wt);

    // 0) transpose weights to [n][k] (tf32-rounded), once per launch
    {
        dim3 blk(32, 8);
        dim3 g1(16, 16, 3);
        transpose_kernel<<<g1, blk>>>(conv_w1, wt1, 512, 512);
        dim3 g2(8, 16, 33);
        transpose_kernel<<<g2, blk>>>(conv_w, wt, 256, 512);
    }

    // 1) embedding + mask
    embed_kernel<<<Mrows, 128>>>(inputs, words, pos, ctab, wtab, ptab,
                                 out + OFF_MASK);

    // 2) conv layers on tf32 mma.sync
    dim3 cgrid(Mrows / 128, 4);
    tconv_kernel<512, 0><<<cgrid, 256>>>(embed, wt1, conv_b1, xa, 1);
    const int dils[11] = {2, 5, 1, 2, 5, 1, 2, 5, 1, 1, 1};
    float* bufs[2] = {xa, xb};
    float* cur = xa;
    for (int i = 0; i < 11; ++i) {
        float* nxt = bufs[(i + 1) & 1];
        tconv_kernel<256, 1><<<cgrid, 256>>>(
            cur, wt + (size_t)i * 3 * 512 * 256, conv_b + i * 512, nxt,
            dils[i]);
        cur = nxt;
    }

    // 3) sub head
    sub_kernel<<<Mrows / 8, 256>>>(cur, sub_w, sub_b, out);

    // 4) BN stats + folded PO head
    zero_sums_kernel<<<1, F3D>>>();
    xstats_kernel<<<256, 256>>>(cur);
    vec_kernel<<<1, 512>>>(cur, subloc);
    finalize_kernel<<<1, F3D>>>(bn_gamma, bn_beta);
    weff_kernel<<<(F3D * P2 + 255) / 256, 256>>>(po_w);
    beff_kernel<<<1, 128>>>(po_w, po_b);
    cvec_kernel<<<Bsz, 128>>>();
    po_kernel<<<Mrows / 16, 256>>>(cur, out);

    (void)in_sizes; (void)n_in; (void)out_size;
}

// round 16
// speedup vs baseline: 3.2954x; 1.0013x over previous
#include <cuda_runtime.h>
#include <cstdint>

// ---------------------------------------------------------------------------
// Problem constants
// ---------------------------------------------------------------------------
#define Bsz   64
#define Ssz   512
#define Mrows (Bsz * Ssz)          // 32768
#define P2    100                  // 2*P
#define F3D   768                  // 3*D

#define OFF_SUB  0
#define OFF_PO   (Bsz * 2 * Ssz)                 // 65536
#define OFF_MASK (OFF_PO + Bsz * P2 * Ssz)       // 3342336

// ---------------------------------------------------------------------------
// Scratch (static __device__ globals; no allocation allowed)
// ---------------------------------------------------------------------------
__device__ float g_embed[(size_t)Mrows * 512];   // 64 MB
__device__ float g_xa[(size_t)Mrows * 256];      // 32 MB
__device__ float g_xb[(size_t)Mrows * 256];      // 32 MB
__device__ float g_maskf[Mrows];
__device__ float g_wt1[3 * 512 * 512];           // conv1 weights transposed [tap][n][k]
__device__ float g_wt[11 * 3 * 512 * 256];       // conv weights transposed
__device__ float g_vec[Bsz * 512];
__device__ float g_sum[F3D];
__device__ float g_sumsq[F3D];
__device__ float g_scale[F3D];
__device__ float g_shift[F3D];
__device__ float g_weff[F3D * P2];
__device__ float g_beff[128];
__device__ float g_c[Bsz * 128];

__device__ __forceinline__ float sigmoidf_(float x) {
    return 1.0f / (1.0f + __expf(-x));
}

__device__ __forceinline__ float tf32r(float x) {
    uint32_t u;
    asm("cvt.rna.tf32.f32 %0, %1;" : "=r"(u) : "f"(x));
    return __uint_as_float(u);
}

__device__ __forceinline__ void mma_tf32(float d[4], const uint32_t a[4],
                                         const uint32_t b[2]) {
    asm volatile(
        "mma.sync.aligned.m16n8k8.row.col.f32.tf32.tf32.f32 "
        "{%0,%1,%2,%3}, {%4,%5,%6,%7}, {%8,%9}, {%0,%1,%2,%3};"
        : "+f"(d[0]), "+f"(d[1]), "+f"(d[2]), "+f"(d[3])
        : "r"(a[0]), "r"(a[1]), "r"(a[2]), "r"(a[3]), "r"(b[0]), "r"(b[1]));
}

// ---------------------------------------------------------------------------
// Embedding + mask
// ---------------------------------------------------------------------------
__global__ void embed_kernel(const int* __restrict__ inputs,
                             const int* __restrict__ words,
                             const int* __restrict__ pos,
                             const float* __restrict__ ctab,
                             const float* __restrict__ wtab,
                             const float* __restrict__ ptab,
                             float* __restrict__ out_mask) {
    int m = blockIdx.x;
    int c = threadIdx.x * 4;
    int ci = inputs[m];
    int wi = words[m];
    int pi = pos[m];
    float4 e;
    if (c < 256) {
        e = *(const float4*)(ctab + (size_t)ci * 256 + c);
    } else {
        e = *(const float4*)(wtab + (size_t)wi * 256 + (c - 256));
    }
    float4 pv = *(const float4*)(ptab + (size_t)pi * 512 + c);
    e.x += pv.x; e.y += pv.y; e.z += pv.z; e.w += pv.w;
    *(float4*)(g_embed + (size_t)m * 512 + c) = e;
    if (threadIdx.x == 0) {
        float mv = (ci != 0) ? 1.0f : 0.0f;
        g_maskf[m]  = mv;
        out_mask[m] = mv;
    }
}

// ---------------------------------------------------------------------------
// Weight transpose: src[z][K][N] -> dst[z][N][K], with tf32 rounding
// ---------------------------------------------------------------------------
__global__ void transpose_kernel(const float* __restrict__ src,
                                 float* __restrict__ dst, int K, int N) {
    __shared__ float t[32][33];
    const float* s = src + (size_t)blockIdx.z * K * N;
    float* d = dst + (size_t)blockIdx.z * K * N;
    int k0 = blockIdx.x * 32, n0 = blockIdx.y * 32;
    int tx = threadIdx.x, ty = threadIdx.y;
#pragma unroll
    for (int i = 0; i < 32; i += 8)
        t[ty + i][tx] = s[(size_t)(k0 + ty + i) * N + n0 + tx];
    __syncthreads();
#pragma unroll
    for (int i = 0; i < 32; i += 8)
        d[(size_t)(n0 + ty + i) * K + k0 + tx] = tf32r(t[tx][ty + i]);
}

// ---------------------------------------------------------------------------
// Gated dilated conv layer on tf32 mma.sync (arch-agnostic PTX).
// Block: 128 rows x 64 output channels. In-block col 2j = gate(ch n0+j),
// col 2j+1 = value(ch n0+j): mma accumulator pairs (c0,c1)/(c2,c3) hold the
// (gate,value) pair for one output channel -> fused gating epilogue.
// 8 warps as 2(m) x 4(n); warp tile 64x32; K-chunk 32 (4 k8 mma steps).
// Smem strides padded to 36 floats -> conflict-free fragment loads.
// ---------------------------------------------------------------------------
template <int CIN, int RES>
__global__ __launch_bounds__(256, 2)
void tconv_kernel(const float* __restrict__ x,
                  const float* __restrict__ wt,     // [3][512][CIN] tf32-rounded
                  const float* __restrict__ bias,   // [512]
                  float* __restrict__ y,
                  int dil) {
    __shared__ float As[128 * 36];
    __shared__ float Bs[128 * 36];
    __shared__ float bias_s[512];

    const int tid  = threadIdx.x;
    const int wid  = tid >> 5;
    const int lane = tid & 31;
    const int l4   = lane & 3;
    const int ld4  = lane >> 2;
    const int m0   = blockIdx.x * 128;
    const int n0   = blockIdx.y * 64;
    const int b    = m0 >> 9;
    const int s0   = m0 & 511;

    const int wm = (wid & 1) * 64;        // warp row offset
    const int wn = (wid >> 1) * 32;       // warp col offset (in-block, 0..127)

    if (tid < 128) ((float4*)bias_s)[tid] = ((const float4*)bias)[tid];

    float d[4][4][4];
#pragma unroll
    for (int mi = 0; mi < 4; ++mi)
#pragma unroll
        for (int ni = 0; ni < 4; ++ni)
#pragma unroll
            for (int r = 0; r < 4; ++r) d[mi][ni][r] = 0.f;

    const int NCK = CIN / 32;
    const int NC  = 3 * NCK;
    const float* xb = x + (size_t)b * 512 * CIN;

    // staging maps: idx = it*256+tid, row/n = idx>>3 (0..127), kg = idx&7
#pragma unroll 1
    for (int c = 0; c < NC; ++c) {
        const int tap = c / NCK;
        const int k0  = (c - tap * NCK) * 32;
        const int off = (tap - 1) * dil;

        __syncthreads();
        // A tile: 128 rows x 32 k, tf32-rounded, OOB rows zero
#pragma unroll
        for (int it = 0; it < 4; ++it) {
            int idx = it * 256 + tid;
            int row = idx >> 3, kg = idx & 7;
            int srow = s0 + row + off;
            float4 v = make_float4(0.f, 0.f, 0.f, 0.f);
            if (srow >= 0 && srow < 512)
                v = *(const float4*)(xb + (size_t)srow * CIN + k0 + kg * 4);
            v.x = tf32r(v.x); v.y = tf32r(v.y);
            v.z = tf32r(v.z); v.w = tf32r(v.w);
            float* p = &As[row * 36 + kg * 4];
            p[0] = v.x; p[1] = v.y; p[2] = v.z; p[3] = v.w;
        }
        // B tile: 128 n-rows (gate/value interleaved) x 32 k
        const float* wtp = wt + (size_t)tap * 512 * CIN + k0;
#pragma unroll
        for (int it = 0; it < 4; ++it) {
            int idx = it * 256 + tid;
            int n = idx >> 3, kg = idx & 7;
            int j = n >> 1;
            int col = (n & 1) ? (n0 + 256 + j) : (n0 + j);
            float4 v = *(const float4*)(wtp + (size_t)col * CIN + kg * 4);
            float* p = &Bs[n * 36 + kg * 4];
            p[0] = v.x; p[1] = v.y; p[2] = v.z; p[3] = v.w;
        }
        __syncthreads();

#pragma unroll
        for (int kk = 0; kk < 4; ++kk) {
            const int kb = kk * 8;
            uint32_t a[4][4];
#pragma unroll
            for (int mi = 0; mi < 4; ++mi) {
                const float* ap = &As[(wm + mi * 16 + ld4) * 36 + kb + l4];
                a[mi][0] = __float_as_uint(ap[0]);
                a[mi][1] = __float_as_uint(ap[8 * 36]);
                a[mi][2] = __float_as_uint(ap[4]);
                a[mi][3] = __float_as_uint(ap[8 * 36 + 4]);
            }
            uint32_t bf[4][2];
#pragma unroll
            for (int ni = 0; ni < 4; ++ni) {
                const float* bp = &Bs[(wn + ni * 8 + ld4) * 36 + kb + l4];
                bf[ni][0] = __float_as_uint(bp[0]);
                bf[ni][1] = __float_as_uint(bp[4]);
            }
#pragma unroll
            for (int mi = 0; mi < 4; ++mi)
#pragma unroll
                for (int ni = 0; ni < 4; ++ni)
                    mma_tf32(d[mi][ni], a[mi], bf[ni]);
        }
    }

    // Epilogue: (c0,c1) = (gate,value) of one channel at row; (c2,c3) at row+8
#pragma unroll
    for (int mi = 0; mi < 4; ++mi) {
        const int row0 = m0 + wm + mi * 16 + ld4;
        const int row1 = row0 + 8;
        const float mk0 = g_maskf[row0];
        const float mk1 = g_maskf[row1];
        const float* xr0 = x + (size_t)row0 * CIN;
        const float* xr1 = x + (size_t)row1 * CIN;
#pragma unroll
        for (int ni = 0; ni < 4; ++ni) {
            const int co = n0 + (wn >> 1) + ni * 4 + l4;   // output channel
            const float bg = bias_s[co];
            const float bv = bias_s[co + 256];
            float g0 = sigmoidf_(d[mi][ni][0] + bg);
            float h0 = d[mi][ni][1] + bv;
            float g1 = sigmoidf_(d[mi][ni][2] + bg);
            float h1 = d[mi][ni][3] + bv;
            float o0, o1;
            if (RES) {
                float x0 = xr0[co], x1 = xr1[co];
                o0 = fmaf(g0, h0 - x0, x0);
                o1 = fmaf(g1, h1 - x1, x1);
            } else {
                o0 = g0 * h0;
                o1 = g1 * h1;
            }
            y[(size_t)row0 * 256 + co] = o0 * mk0;
            y[(size_t)row1 * 256 + co] = o1 * mk1;
        }
    }
}

// ---------------------------------------------------------------------------
// sub head
// ---------------------------------------------------------------------------
__global__ void sub_kernel(const float* __restrict__ x,
                           const float* __restrict__ sw,
                           const float* __restrict__ sb,
                           float* __restrict__ out) {
    int warp = threadIdx.x >> 5;
    int lane = threadIdx.x & 31;
    int m = blockIdx.x * 8 + warp;
    const float* xr = x + (size_t)m * 256;
    float a0 = 0.f, a1 = 0.f;
#pragma unroll
    for (int w = 0; w < 8; ++w) {
        int k = lane + w * 32;
        float xv = xr[k];
        a0 = fmaf(xv, sw[k * 2 + 0], a0);
        a1 = fmaf(xv, sw[k * 2 + 1], a1);
    }
#pragma unroll
    for (int o = 16; o; o >>= 1) {
        a0 += __shfl_xor_sync(0xffffffffu, a0, o);
        a1 += __shfl_xor_sync(0xffffffffu, a1, o);
    }
    if (lane == 0) {
        int b = m >> 9, s = m & 511;
        out[OFF_SUB + b * 1024 + s]       = sigmoidf_(a0 + sb[0]);
        out[OFF_SUB + b * 1024 + 512 + s] = sigmoidf_(a1 + sb[1]);
    }
}

// ---------------------------------------------------------------------------
// BN statistics + PO weight folding
// ---------------------------------------------------------------------------
__global__ void zero_sums_kernel() {
    int f = threadIdx.x;
    if (f < F3D) { g_sum[f] = 0.f; g_sumsq[f] = 0.f; }
}

__global__ void xstats_kernel(const float* __restrict__ x) {
    int t  = threadIdx.x;
    int r0 = blockIdx.x * 128;
    float s = 0.f, q = 0.f;
    for (int r = 0; r < 128; ++r) {
        float v = x[(size_t)(r0 + r) * 256 + t];
        s += v; q += v * v;
    }
    atomicAdd(&g_sum[t], s);
    atomicAdd(&g_sumsq[t], q);
}

__global__ void vec_kernel(const float* __restrict__ x,
                           const int* __restrict__ subloc) {
    int f = threadIdx.x;
    int half = f >> 8;
    int fi = f & 255;
    float s = 0.f, q = 0.f;
    for (int b = 0; b < 64; ++b) {
        int loc = subloc[b * 2 + half];
        float v = x[(size_t)((b << 9) + loc) * 256 + fi];
        g_vec[b * 512 + f] = v;
        s += v; q += v * v;
    }
    g_sum[256 + f] = s;
    g_sumsq[256 + f] = q;
}

__global__ void finalize_kernel(const float* __restrict__ gamma,
                                const float* __restrict__ beta) {
    int f = threadIdx.x;
    if (f >= F3D) return;
    float n   = (f < 256) ? 32768.0f : 64.0f;
    float mu  = g_sum[f] / n;
    float var = g_sumsq[f] / n - mu * mu;
    float sc  = gamma[f] * rsqrtf(var + 0.001f);
    g_scale[f] = sc;
    g_shift[f] = beta[f] - mu * sc;
}

__global__ void weff_kernel(const float* __restrict__ po_w) {
    int idx = blockIdx.x * 256 + threadIdx.x;
    if (idx < F3D * P2) g_weff[idx] = po_w[idx] * g_scale[idx / P2];
}

__global__ void beff_kernel(const float* __restrict__ po_w,
                            const float* __restrict__ po_b) {
    int p = threadIdx.x;
    if (p >= P2) return;
    float acc = po_b[p];
    for (int f = 0; f < F3D; ++f) acc = fmaf(g_shift[f], po_w[f * P2 + p], acc);
    g_beff[p] = acc;
}

__global__ void cvec_kernel() {
    int b = blockIdx.x;
    int p = threadIdx.x;
    if (p >= P2) return;
    float acc = 0.f;
    for (int f = 0; f < 512; ++f)
        acc = fmaf(g_vec[b * 512 + f], g_weff[(256 + f) * P2 + p], acc);
    g_c[b * 128 + p] = acc;
}

__global__ __launch_bounds__(256)
void po_kernel(const float* __restrict__ x, float* __restrict__ out) {
    __shared__ float xs[16 * 256];
    int m0 = blockIdx.x * 16;
    const float* xg = x + (size_t)m0 * 256;
#pragma unroll
    for (int v = 0; v < 4; ++v) {
        int off = threadIdx.x * 4 + v * 1024;
        *(float4*)&xs[off] = *(const float4*)(xg + off);
    }
    __syncthreads();

    int p  = threadIdx.x & 127;
    int rg = threadIdx.x >> 7;
    if (p < P2) {
        float acc[8];
#pragma unroll
        for (int i = 0; i < 8; ++i) acc[i] = 0.f;
        for (int k = 0; k < 256; ++k) {
            float wv = g_weff[k * P2 + p];
#pragma unroll
            for (int i = 0; i < 8; ++i)
                acc[i] = fmaf(xs[(rg + i * 2) * 256 + k], wv, acc[i]);
        }
        float be = g_beff[p];
#pragma unroll
        for (int i = 0; i < 8; ++i) {
            int m = m0 + rg + i * 2;
            int b = m >> 9, s = m & 511;
            out[OFF_PO + ((size_t)b * P2 + p) * 512 + s] =
                sigmoidf_(acc[i] + g_c[b * 128 + p] + be);
        }
    }
}

// ---------------------------------------------------------------------------
// kernel_launch
// ---------------------------------------------------------------------------
extern "C" void kernel_launch(void* const* d_in, const int* in_sizes, int n_in,
                              void* d_out, int out_size) {
    const int*   inputs   = (const int*)d_in[0];
    const int*   words    = (const int*)d_in[1];
    const int*   pos      = (const int*)d_in[2];
    const int*   subloc   = (const int*)d_in[3];
    const float* ctab     = (const float*)d_in[4];
    const float* wtab     = (const float*)d_in[5];
    const float* ptab     = (const float*)d_in[6];
    const float* conv_w1  = (const float*)d_in[7];
    const float* conv_b1  = (const float*)d_in[8];
    const float* conv_w   = (const float*)d_in[9];
    const float* conv_b   = (const float*)d_in[10];
    const float* sub_w    = (const float*)d_in[11];
    const float* sub_b    = (const float*)d_in[12];
    const float* po_w     = (const float*)d_in[13];
    const float* po_b     = (const float*)d_in[14];
    const float* bn_gamma = (const float*)d_in[15];
    const float* bn_beta  = (const float*)d_in[16];
    float* out = (float*)d_out;

    float *embed = nullptr, *xa = nullptr, *xb = nullptr;
    float *wt1 = nullptr, *wt = nullptr;
    cudaGetSymbolAddress((void**)&embed, g_embed);
    cudaGetSymbolAddress((void**)&xa, g_xa);
    cudaGetSymbolAddress((void**)&xb, g_xb);
    cudaGetSymbolAddress((void**)&wt1, g_wt1);
    cudaGetSymbolAddress((void**)&wt, g_wt);

    // 0) transpose weights to [n][k] (tf32-rounded), once per launch
    {
        dim3 blk(32, 8);
        dim3 g1(16, 16, 3);
        transpose_kernel<<<g1, blk>>>(conv_w1, wt1, 512, 512);
        dim3 g2(8, 16, 33);
        transpose_kernel<<<g2, blk>>>(conv_w, wt, 256, 512);
    }

    // 1) embedding + mask
    embed_kernel<<<Mrows, 128>>>(inputs, words, pos, ctab, wtab, ptab,
                                 out + OFF_MASK);

    // 2) conv layers on tf32 mma.sync
    dim3 cgrid(Mrows / 128, 4);
    tconv_kernel<512, 0><<<cgrid, 256>>>(embed, wt1, conv_b1, xa, 1);
    const int dils[11] = {2, 5, 1, 2, 5, 1, 2, 5, 1, 1, 1};
    float* bufs[2] = {xa, xb};
    float* cur = xa;
    for (int i = 0; i < 11; ++i) {
        float* nxt = bufs[(i + 1) & 1];
        tconv_kernel<256, 1><<<cgrid, 256>>>(
            cur, wt + (size_t)i * 3 * 512 * 256, conv_b + i * 512, nxt,
            dils[i]);
        cur = nxt;
    }

    // 3) sub head
    sub_kernel<<<Mrows / 8, 256>>>(cur, sub_w, sub_b, out);

    // 4) BN stats + folded PO head
    zero_sums_kernel<<<1, F3D>>>();
    xstats_kernel<<<256, 256>>>(cur);
    vec_kernel<<<1, 512>>>(cur, subloc);
    finalize_kernel<<<1, F3D>>>(bn_gamma, bn_beta);
    weff_kernel<<<(F3D * P2 + 255) / 256, 256>>>(po_w);
    beff_kernel<<<1, 128>>>(po_w, po_b);
    cvec_kernel<<<Bsz, 128>>>();
    po_kernel<<<Mrows / 16, 256>>>(cur, out);

    (void)in_sizes; (void)n_in; (void)out_size;
}

// round 17
// speedup vs baseline: 5.1992x; 1.5777x over previous
#include <cuda_runtime.h>
#include <cuda_bf16.h>
#include <cstdint>

// ---------------------------------------------------------------------------
// Problem constants
// ---------------------------------------------------------------------------
#define Bsz   64
#define Ssz   512
#define Mrows (Bsz * Ssz)          // 32768
#define P2    100                  // 2*P
#define F3D   768                  // 3*D

#define OFF_SUB  0
#define OFF_PO   (Bsz * 2 * Ssz)                 // 65536
#define OFF_MASK (OFF_PO + Bsz * P2 * Ssz)       // 3342336

// ---------------------------------------------------------------------------
// Scratch (static __device__ globals; no allocation allowed)
// ---------------------------------------------------------------------------
__device__ __align__(128) __nv_bfloat16 g_eh[(size_t)Mrows * 512];   // embed bf16
__device__ float g_xa[(size_t)Mrows * 256];      // fp32 master activations
__device__ float g_xb[(size_t)Mrows * 256];
__device__ __align__(128) __nv_bfloat16 g_xha[(size_t)Mrows * 256]; // bf16 shadows
__device__ __align__(128) __nv_bfloat16 g_xhb[(size_t)Mrows * 256];
__device__ float g_maskf[Mrows];
__device__ __align__(128) __nv_bfloat16 g_wt1h[3 * 512 * 512];      // conv1 W^T bf16
__device__ __align__(128) __nv_bfloat16 g_wth[11 * 3 * 512 * 256];  // conv W^T bf16
__device__ float g_vec[Bsz * 512];
__device__ float g_sum[F3D];
__device__ float g_sumsq[F3D];
__device__ float g_scale[F3D];
__device__ float g_shift[F3D];
__device__ float g_weff[F3D * P2];
__device__ float g_beff[128];
__device__ float g_c[Bsz * 128];

__device__ __forceinline__ float sigmoidf_(float x) {
    return 1.0f / (1.0f + __expf(-x));
}

__device__ __forceinline__ void mma_bf16(float d[4], const uint32_t a[4],
                                         const uint32_t b[2]) {
    asm volatile(
        "mma.sync.aligned.m16n8k16.row.col.f32.bf16.bf16.f32 "
        "{%0,%1,%2,%3}, {%4,%5,%6,%7}, {%8,%9}, {%0,%1,%2,%3};"
        : "+f"(d[0]), "+f"(d[1]), "+f"(d[2]), "+f"(d[3])
        : "r"(a[0]), "r"(a[1]), "r"(a[2]), "r"(a[3]), "r"(b[0]), "r"(b[1]));
}

__device__ __forceinline__ uint32_t smem_u32(const void* p) {
    uint32_t a;
    asm("{ .reg .u64 t; cvta.to.shared.u64 t, %1; cvt.u32.u64 %0, t; }"
        : "=r"(a) : "l"(p));
    return a;
}

__device__ __forceinline__ void cp16(uint32_t dst, const void* src) {
    asm volatile("cp.async.ca.shared.global [%0], [%1], 16;"
                 :: "r"(dst), "l"(src) : "memory");
}
__device__ __forceinline__ void cp16z(uint32_t dst, const void* src) {
    asm volatile("cp.async.ca.shared.global [%0], [%1], 16, 0;"
                 :: "r"(dst), "l"(src) : "memory");
}

// ---------------------------------------------------------------------------
// Embedding (bf16) + mask
// ---------------------------------------------------------------------------
__global__ void embed_kernel(const int* __restrict__ inputs,
                             const int* __restrict__ words,
                             const int* __restrict__ pos,
                             const float* __restrict__ ctab,
                             const float* __restrict__ wtab,
                             const float* __restrict__ ptab,
                             float* __restrict__ out_mask) {
    int m = blockIdx.x;
    int c = threadIdx.x * 4;
    int ci = inputs[m];
    int wi = words[m];
    int pi = pos[m];
    float4 e;
    if (c < 256) {
        e = *(const float4*)(ctab + (size_t)ci * 256 + c);
    } else {
        e = *(const float4*)(wtab + (size_t)wi * 256 + (c - 256));
    }
    float4 pv = *(const float4*)(ptab + (size_t)pi * 512 + c);
    e.x += pv.x; e.y += pv.y; e.z += pv.z; e.w += pv.w;
    __nv_bfloat162 lo = __floats2bfloat162_rn(e.x, e.y);
    __nv_bfloat162 hi = __floats2bfloat162_rn(e.z, e.w);
    __nv_bfloat162* p = (__nv_bfloat162*)(g_eh + (size_t)m * 512 + c);
    p[0] = lo; p[1] = hi;
    if (threadIdx.x == 0) {
        float mv = (ci != 0) ? 1.0f : 0.0f;
        g_maskf[m]  = mv;
        out_mask[m] = mv;
    }
}

// ---------------------------------------------------------------------------
// Weight transpose: src[z][K][N] fp32 -> dst[z][N][K] bf16
// ---------------------------------------------------------------------------
__global__ void transpose_kernel(const float* __restrict__ src,
                                 __nv_bfloat16* __restrict__ dst, int K, int N) {
    __shared__ float t[32][33];
    const float* s = src + (size_t)blockIdx.z * K * N;
    __nv_bfloat16* d = dst + (size_t)blockIdx.z * K * N;
    int k0 = blockIdx.x * 32, n0 = blockIdx.y * 32;
    int tx = threadIdx.x, ty = threadIdx.y;
#pragma unroll
    for (int i = 0; i < 32; i += 8)
        t[ty + i][tx] = s[(size_t)(k0 + ty + i) * N + n0 + tx];
    __syncthreads();
#pragma unroll
    for (int i = 0; i < 32; i += 8)
        d[(size_t)(n0 + ty + i) * K + k0 + tx] = __float2bfloat16(t[tx][ty + i]);
}

// ---------------------------------------------------------------------------
// Gated dilated conv layer on bf16 mma.sync m16n8k16, cp.async double-buffered.
// Block: 128 rows x 64 output channels (gate/value interleaved in B rows).
// 8 warps as 2(m) x 4(n); warp tile 64x32; K-chunk 64 (4 k16 mma steps).
// Smem rows padded to 36 uint32 (144B) -> conflict-free, 16B-aligned cp.async.
// ---------------------------------------------------------------------------
#define SM_A0 2048
#define SM_A1 20480
#define SM_B0 38912
#define SM_B1 57344
#define SM_TOT 75776

template <int CIN, int RES>
__global__ __launch_bounds__(256, 2)
void tconv_kernel(const float* __restrict__ x,             // fp32 (residual), may be unused
                  const __nv_bfloat16* __restrict__ xh,    // bf16 activations
                  const __nv_bfloat16* __restrict__ wt,    // [3][512][CIN] bf16
                  const float* __restrict__ bias,          // [512]
                  float* __restrict__ y,
                  __nv_bfloat16* __restrict__ yh,
                  int dil) {
    extern __shared__ char smem[];
    float* bias_s = (float*)smem;
    const uint32_t sb = smem_u32(smem);

    const int tid  = threadIdx.x;
    const int wid  = tid >> 5;
    const int lane = tid & 31;
    const int t4   = lane & 3;
    const int g    = lane >> 2;
    const int m0   = blockIdx.x * 128;
    const int n0   = blockIdx.y * 64;
    const int b    = m0 >> 9;
    const int s0   = m0 & 511;
    const int wm   = (wid & 1) * 64;
    const int wn   = (wid >> 1) * 32;

    if (tid < 128) ((float4*)bias_s)[tid] = ((const float4*)bias)[tid];

    float d[4][4][4];
#pragma unroll
    for (int mi = 0; mi < 4; ++mi)
#pragma unroll
        for (int ni = 0; ni < 4; ++ni)
#pragma unroll
            for (int r = 0; r < 4; ++r) d[mi][ni][r] = 0.f;

    const int NCK = CIN / 64;
    const int NC  = 3 * NCK;
    const __nv_bfloat16* xbh = xh + (size_t)b * 512 * CIN;

    const int srw = tid >> 3;     // staging row within 32-row group
    const int cg  = tid & 7;      // 16B granule within row (8 bf16)

    auto stage = [&](int c, int buf) {
        const int tap = c / NCK;
        const int k0  = (c - tap * NCK) * 64;
        const int off = (tap - 1) * dil;
        const uint32_t da = sb + (buf ? SM_A1 : SM_A0);
        const uint32_t db = sb + (buf ? SM_B1 : SM_B0);
        const __nv_bfloat16* wtp = wt + (size_t)tap * 512 * CIN + k0;
#pragma unroll
        for (int it = 0; it < 4; ++it) {
            int row  = it * 32 + srw;
            int srow = s0 + row + off;
            uint32_t dst = da + row * 144 + cg * 16;
            if (srow >= 0 && srow < 512)
                cp16(dst, xbh + (size_t)srow * CIN + k0 + cg * 8);
            else
                cp16z(dst, xbh);
        }
#pragma unroll
        for (int it = 0; it < 4; ++it) {
            int n = it * 32 + srw;
            int j = n >> 1;
            int col = (n & 1) ? (n0 + 256 + j) : (n0 + j);
            cp16(db + n * 144 + cg * 16, wtp + (size_t)col * CIN + cg * 8);
        }
    };

    stage(0, 0);
    asm volatile("cp.async.commit_group;" ::: "memory");

#pragma unroll 1
    for (int c = 0; c < NC; ++c) {
        if (c + 1 < NC) stage(c + 1, (c + 1) & 1);
        asm volatile("cp.async.commit_group;" ::: "memory");
        asm volatile("cp.async.wait_group 1;" ::: "memory");
        __syncthreads();

        const uint32_t* As =
            (const uint32_t*)(smem + ((c & 1) ? SM_A1 : SM_A0));
        const uint32_t* Bs =
            (const uint32_t*)(smem + ((c & 1) ? SM_B1 : SM_B0));

#pragma unroll
        for (int kk = 0; kk < 4; ++kk) {
            const int kb = kk * 8;     // uint32 (bf16-pair) offset
            uint32_t a[4][4];
#pragma unroll
            for (int mi = 0; mi < 4; ++mi) {
                const uint32_t* ap = &As[(wm + mi * 16 + g) * 36 + kb + t4];
                a[mi][0] = ap[0];
                a[mi][1] = ap[8 * 36];
                a[mi][2] = ap[4];
                a[mi][3] = ap[8 * 36 + 4];
            }
            uint32_t bf[4][2];
#pragma unroll
            for (int ni = 0; ni < 4; ++ni) {
                const uint32_t* bp = &Bs[(wn + ni * 8 + g) * 36 + kb];
                bf[ni][0] = bp[t4];
                bf[ni][1] = bp[t4 + 4];
            }
#pragma unroll
            for (int mi = 0; mi < 4; ++mi)
#pragma unroll
                for (int ni = 0; ni < 4; ++ni)
                    mma_bf16(d[mi][ni], a[mi], bf[ni]);
        }
        __syncthreads();
    }

    // Epilogue: (c0,c1)=(gate,value) of one channel at row0; (c2,c3) at row0+8
#pragma unroll
    for (int mi = 0; mi < 4; ++mi) {
        const int row0 = m0 + wm + mi * 16 + g;
        const int row1 = row0 + 8;
        const float mk0 = g_maskf[row0];
        const float mk1 = g_maskf[row1];
        const float* xr0 = x + (size_t)row0 * 256;
        const float* xr1 = x + (size_t)row1 * 256;
#pragma unroll
        for (int ni = 0; ni < 4; ++ni) {
            const int co = n0 + (wn >> 1) + ni * 4 + t4;
            const float bg = bias_s[co];
            const float bv = bias_s[co + 256];
            float g0 = sigmoidf_(d[mi][ni][0] + bg);
            float h0 = d[mi][ni][1] + bv;
            float g1 = sigmoidf_(d[mi][ni][2] + bg);
            float h1 = d[mi][ni][3] + bv;
            float o0, o1;
            if (RES) {
                float x0 = xr0[co], x1 = xr1[co];
                o0 = fmaf(g0, h0 - x0, x0);
                o1 = fmaf(g1, h1 - x1, x1);
            } else {
                o0 = g0 * h0;
                o1 = g1 * h1;
            }
            o0 *= mk0; o1 *= mk1;
            y[(size_t)row0 * 256 + co] = o0;
            y[(size_t)row1 * 256 + co] = o1;
            yh[(size_t)row0 * 256 + co] = __float2bfloat16(o0);
            yh[(size_t)row1 * 256 + co] = __float2bfloat16(o1);
        }
    }
}

// ---------------------------------------------------------------------------
// sub head
// ---------------------------------------------------------------------------
__global__ void sub_kernel(const float* __restrict__ x,
                           const float* __restrict__ sw,
                           const float* __restrict__ sb,
                           float* __restrict__ out) {
    int warp = threadIdx.x >> 5;
    int lane = threadIdx.x & 31;
    int m = blockIdx.x * 8 + warp;
    const float* xr = x + (size_t)m * 256;
    float a0 = 0.f, a1 = 0.f;
#pragma unroll
    for (int w = 0; w < 8; ++w) {
        int k = lane + w * 32;
        float xv = xr[k];
        a0 = fmaf(xv, sw[k * 2 + 0], a0);
        a1 = fmaf(xv, sw[k * 2 + 1], a1);
    }
#pragma unroll
    for (int o = 16; o; o >>= 1) {
        a0 += __shfl_xor_sync(0xffffffffu, a0, o);
        a1 += __shfl_xor_sync(0xffffffffu, a1, o);
    }
    if (lane == 0) {
        int b = m >> 9, s = m & 511;
        out[OFF_SUB + b * 1024 + s]       = sigmoidf_(a0 + sb[0]);
        out[OFF_SUB + b * 1024 + 512 + s] = sigmoidf_(a1 + sb[1]);
    }
}

// ---------------------------------------------------------------------------
// BN statistics + PO weight folding
// ---------------------------------------------------------------------------
__global__ void zero_sums_kernel() {
    int f = threadIdx.x;
    if (f < F3D) { g_sum[f] = 0.f; g_sumsq[f] = 0.f; }
}

__global__ void xstats_kernel(const float* __restrict__ x) {
    int t  = threadIdx.x;
    int r0 = blockIdx.x * 128;
    float s = 0.f, q = 0.f;
    for (int r = 0; r < 128; ++r) {
        float v = x[(size_t)(r0 + r) * 256 + t];
        s += v; q += v * v;
    }
    atomicAdd(&g_sum[t], s);
    atomicAdd(&g_sumsq[t], q);
}

__global__ void vec_kernel(const float* __restrict__ x,
                           const int* __restrict__ subloc) {
    int f = threadIdx.x;
    int half = f >> 8;
    int fi = f & 255;
    float s = 0.f, q = 0.f;
    for (int b = 0; b < 64; ++b) {
        int loc = subloc[b * 2 + half];
        float v = x[(size_t)((b << 9) + loc) * 256 + fi];
        g_vec[b * 512 + f] = v;
        s += v; q += v * v;
    }
    g_sum[256 + f] = s;
    g_sumsq[256 + f] = q;
}

__global__ void finalize_kernel(const float* __restrict__ gamma,
                                const float* __restrict__ beta) {
    int f = threadIdx.x;
    if (f >= F3D) return;
    float n   = (f < 256) ? 32768.0f : 64.0f;
    float mu  = g_sum[f] / n;
    float var = g_sumsq[f] / n - mu * mu;
    float sc  = gamma[f] * rsqrtf(var + 0.001f);
    g_scale[f] = sc;
    g_shift[f] = beta[f] - mu * sc;
}

__global__ void weff_kernel(const float* __restrict__ po_w) {
    int idx = blockIdx.x * 256 + threadIdx.x;
    if (idx < F3D * P2) g_weff[idx] = po_w[idx] * g_scale[idx / P2];
}

__global__ void beff_kernel(const float* __restrict__ po_w,
                            const float* __restrict__ po_b) {
    int p = threadIdx.x;
    if (p >= P2) return;
    float acc = po_b[p];
    for (int f = 0; f < F3D; ++f) acc = fmaf(g_shift[f], po_w[f * P2 + p], acc);
    g_beff[p] = acc;
}

__global__ void cvec_kernel() {
    int b = blockIdx.x;
    int p = threadIdx.x;
    if (p >= P2) return;
    float acc = 0.f;
    for (int f = 0; f < 512; ++f)
        acc = fmaf(g_vec[b * 512 + f], g_weff[(256 + f) * P2 + p], acc);
    g_c[b * 128 + p] = acc;
}

__global__ __launch_bounds__(256)
void po_kernel(const float* __restrict__ x, float* __restrict__ out) {
    __shared__ float xs[16 * 256];
    int m0 = blockIdx.x * 16;
    const float* xg = x + (size_t)m0 * 256;
#pragma unroll
    for (int v = 0; v < 4; ++v) {
        int off = threadIdx.x * 4 + v * 1024;
        *(float4*)&xs[off] = *(const float4*)(xg + off);
    }
    __syncthreads();

    int p  = threadIdx.x & 127;
    int rg = threadIdx.x >> 7;
    if (p < P2) {
        float acc[8];
#pragma unroll
        for (int i = 0; i < 8; ++i) acc[i] = 0.f;
        for (int k = 0; k < 256; ++k) {
            float wv = g_weff[k * P2 + p];
#pragma unroll
            for (int i = 0; i < 8; ++i)
                acc[i] = fmaf(xs[(rg + i * 2) * 256 + k], wv, acc[i]);
        }
        float be = g_beff[p];
#pragma unroll
        for (int i = 0; i < 8; ++i) {
            int m = m0 + rg + i * 2;
            int b = m >> 9, s = m & 511;
            out[OFF_PO + ((size_t)b * P2 + p) * 512 + s] =
                sigmoidf_(acc[i] + g_c[b * 128 + p] + be);
        }
    }
}

// ---------------------------------------------------------------------------
// kernel_launch
// ---------------------------------------------------------------------------
extern "C" void kernel_launch(void* const* d_in, const int* in_sizes, int n_in,
                              void* d_out, int out_size) {
    const int*   inputs   = (const int*)d_in[0];
    const int*   words    = (const int*)d_in[1];
    const int*   pos      = (const int*)d_in[2];
    const int*   subloc   = (const int*)d_in[3];
    const float* ctab     = (const float*)d_in[4];
    const float* wtab     = (const float*)d_in[5];
    const float* ptab     = (const float*)d_in[6];
    const float* conv_w1  = (const float*)d_in[7];
    const float* conv_b1  = (const float*)d_in[8];
    const float* conv_w   = (const float*)d_in[9];
    const float* conv_b   = (const float*)d_in[10];
    const float* sub_w    = (const float*)d_in[11];
    const float* sub_b    = (const float*)d_in[12];
    const float* po_w     = (const float*)d_in[13];
    const float* po_b     = (const float*)d_in[14];
    const float* bn_gamma = (const float*)d_in[15];
    const float* bn_beta  = (const float*)d_in[16];
    float* out = (float*)d_out;

    __nv_bfloat16 *eh = nullptr, *xha = nullptr, *xhb = nullptr;
    __nv_bfloat16 *wt1h = nullptr, *wth = nullptr;
    float *xa = nullptr, *xb = nullptr;
    cudaGetSymbolAddress((void**)&eh, g_eh);
    cudaGetSymbolAddress((void**)&xa, g_xa);
    cudaGetSymbolAddress((void**)&xb, g_xb);
    cudaGetSymbolAddress((void**)&xha, g_xha);
    cudaGetSymbolAddress((void**)&xhb, g_xhb);
    cudaGetSymbolAddress((void**)&wt1h, g_wt1h);
    cudaGetSymbolAddress((void**)&wth, g_wth);

    cudaFuncSetAttribute(tconv_kernel<512, 0>,
                         cudaFuncAttributeMaxDynamicSharedMemorySize, SM_TOT);
    cudaFuncSetAttribute(tconv_kernel<256, 1>,
                         cudaFuncAttributeMaxDynamicSharedMemorySize, SM_TOT);

    // 0) transpose weights to [n][k] bf16, once per launch
    {
        dim3 blk(32, 8);
        dim3 g1(16, 16, 3);
        transpose_kernel<<<g1, blk>>>(conv_w1, wt1h, 512, 512);
        dim3 g2(8, 16, 33);
        transpose_kernel<<<g2, blk>>>(conv_w, wth, 256, 512);
    }

    // 1) embedding + mask
    embed_kernel<<<Mrows, 128>>>(inputs, words, pos, ctab, wtab, ptab,
                                 out + OFF_MASK);

    // 2) conv layers on bf16 mma.sync (double-buffered cp.async)
    dim3 cgrid(Mrows / 128, 4);
    tconv_kernel<512, 0><<<cgrid, 256, SM_TOT>>>(xa /*unused*/, eh, wt1h,
                                                 conv_b1, xa, xha, 1);
    const int dils[11] = {2, 5, 1, 2, 5, 1, 2, 5, 1, 1, 1};
    float* bufs[2] = {xa, xb};
    __nv_bfloat16* bufsh[2] = {xha, xhb};
    float* cur = xa;
    __nv_bfloat16* curh = xha;
    for (int i = 0; i < 11; ++i) {
        float* nxt = bufs[(i + 1) & 1];
        __nv_bfloat16* nxth = bufsh[(i + 1) & 1];
        tconv_kernel<256, 1><<<cgrid, 256, SM_TOT>>>(
            cur, curh, wth + (size_t)i * 3 * 512 * 256, conv_b + i * 512, nxt,
            nxth, dils[i]);
        cur = nxt; curh = nxth;
    }

    // 3) sub head
    sub_kernel<<<Mrows / 8, 256>>>(cur, sub_w, sub_b, out);

    // 4) BN stats + folded PO head
    zero_sums_kernel<<<1, F3D>>>();
    xstats_kernel<<<256, 256>>>(cur);
    vec_kernel<<<1, 512>>>(cur, subloc);
    finalize_kernel<<<1, F3D>>>(bn_gamma, bn_beta);
    weff_kernel<<<(F3D * P2 + 255) / 256, 256>>>(po_w);
    beff_kernel<<<1, 128>>>(po_w, po_b);
    cvec_kernel<<<Bsz, 128>>>();
    po_kernel<<<Mrows / 16, 256>>>(cur, out);

    (void)in_sizes; (void)n_in; (void)out_size;
}